// round 1
// baseline (speedup 1.0000x reference)
#include <cuda_runtime.h>
#include <cuda_bf16.h>

// Problem constants (fixed by setup_inputs)
#define BB 4
#define LL 4096
#define DD 1024
#define HH 16
#define MM 4
#define DK 64
#define NTOK (BB * LL)          // 16384 rows for projection GEMMs

// Scratch: __device__ globals (no cudaMalloc allowed)
__device__ float g_Q[(size_t)NTOK * DD];
__device__ float g_K[(size_t)NTOK * DD];
__device__ float g_V[(size_t)NTOK * DD];
__device__ float g_O[(size_t)NTOK * DD];

// ---------------------------------------------------------------------------
// SGEMM: C[M,N] = A[M,K] @ B[K,N] + bias[N]   (all row-major, fp32)
// 128x128 tile, BK=8, 256 threads, 8x8 register tile per thread.
// ---------------------------------------------------------------------------
__global__ __launch_bounds__(256) void sgemm_bias(
    const float* __restrict__ A, const float* __restrict__ B,
    const float* __restrict__ bias, float* __restrict__ C,
    int Mr, int Nr, int Kr)
{
    __shared__ float As[8][132];   // transposed A tile, padded
    __shared__ float Bs[8][132];   // B tile, padded

    const int tid  = threadIdx.x;
    const int cRow = blockIdx.y * 128;
    const int cCol = blockIdx.x * 128;
    const int tr   = tid >> 4;     // 0..15
    const int tc   = tid & 15;     // 0..15

    // load indices
    const int aRow = tid >> 1;            // 0..127
    const int aCol = (tid & 1) * 4;       // 0 or 4
    const int bRow = tid >> 5;            // 0..7
    const int bCol = (tid & 31) * 4;      // 0..124

    float acc[8][8];
    #pragma unroll
    for (int r = 0; r < 8; ++r)
        #pragma unroll
        for (int c = 0; c < 8; ++c) acc[r][c] = 0.f;

    for (int kb = 0; kb < Kr; kb += 8) {
        // load A tile (transposed into smem)
        float4 av = *reinterpret_cast<const float4*>(
            &A[(size_t)(cRow + aRow) * Kr + kb + aCol]);
        As[aCol + 0][aRow] = av.x;
        As[aCol + 1][aRow] = av.y;
        As[aCol + 2][aRow] = av.z;
        As[aCol + 3][aRow] = av.w;
        // load B tile
        float4 bv = *reinterpret_cast<const float4*>(
            &B[(size_t)(kb + bRow) * Nr + cCol + bCol]);
        *reinterpret_cast<float4*>(&Bs[bRow][bCol]) = bv;
        __syncthreads();

        #pragma unroll
        for (int k = 0; k < 8; ++k) {
            float ra[8], rb[8];
            *reinterpret_cast<float4*>(&ra[0]) =
                *reinterpret_cast<const float4*>(&As[k][tr * 8]);
            *reinterpret_cast<float4*>(&ra[4]) =
                *reinterpret_cast<const float4*>(&As[k][tr * 8 + 4]);
            *reinterpret_cast<float4*>(&rb[0]) =
                *reinterpret_cast<const float4*>(&Bs[k][tc * 8]);
            *reinterpret_cast<float4*>(&rb[4]) =
                *reinterpret_cast<const float4*>(&Bs[k][tc * 8 + 4]);
            #pragma unroll
            for (int r = 0; r < 8; ++r)
                #pragma unroll
                for (int c = 0; c < 8; ++c)
                    acc[r][c] += ra[r] * rb[c];
        }
        __syncthreads();
    }

    // epilogue: add bias, store
    #pragma unroll
    for (int r = 0; r < 8; ++r) {
        const size_t rowOff = (size_t)(cRow + tr * 8 + r) * Nr + cCol + tc * 8;
        #pragma unroll
        for (int c4 = 0; c4 < 8; c4 += 4) {
            float4 bi = *reinterpret_cast<const float4*>(&bias[cCol + tc * 8 + c4]);
            float4 ov;
            ov.x = acc[r][c4 + 0] + bi.x;
            ov.y = acc[r][c4 + 1] + bi.y;
            ov.z = acc[r][c4 + 2] + bi.z;
            ov.w = acc[r][c4 + 3] + bi.w;
            *reinterpret_cast<float4*>(&C[rowOff + c4]) = ov;
        }
    }
}

// ---------------------------------------------------------------------------
// Strided-slice flash attention.
// Slice (b,h,m): tokens t = j*M + m, j in [0,1024), head h (cols h*64..h*64+63).
// Grid: x = q-block (16 blocks of 64 q rows), y = slice id (256).
// CTA: 256 threads as 16x16 grid, each owning a 4(row)x4(col) tile.
// Streams K/V in 64-row chunks with online softmax.
// ---------------------------------------------------------------------------
__global__ __launch_bounds__(256) void attn_kernel(
    const float* __restrict__ Q, const float* __restrict__ K,
    const float* __restrict__ V, float* __restrict__ O)
{
    extern __shared__ float sm[];
    float* qst = sm;               // [64][68]  q transposed (pre-scaled): qst[d][i]
    float* kst = sm + 64 * 68;     // [64][68]  k transposed: kst[d][j]
    float* vs  = sm + 2 * 64 * 68; // [64][68]  v row-major:  vs[j][d]
    float* ps  = sm + 3 * 64 * 68; // [64][68]  p row-major:  ps[i][j]

    int sl = blockIdx.y;
    const int m = sl & 3;
    const int h = (sl >> 2) & 15;
    const int b = sl >> 6;
    const int qb = blockIdx.x;
    const int tid = threadIdx.x;
    const int ty = tid >> 4;       // 0..15 -> q rows ty*4..ty*4+3
    const int tx = tid & 15;       // 0..15 -> cols   tx*4..tx*4+3

    const size_t headBase = ((size_t)b * LL) * DD + (size_t)h * DK;

    // load Q tile transposed & pre-scaled by 1/sqrt(dk)=0.125
    {
        const int row = tid >> 4;
        const int c4  = (tid & 15) * 4;
        #pragma unroll
        for (int it = 0; it < 4; ++it) {
            const int i = it * 16 + row;
            const int tok = (qb * 64 + i) * MM + m;
            float4 v4 = *reinterpret_cast<const float4*>(
                &Q[headBase + (size_t)tok * DD + c4]);
            qst[(c4 + 0) * 68 + i] = v4.x * 0.125f;
            qst[(c4 + 1) * 68 + i] = v4.y * 0.125f;
            qst[(c4 + 2) * 68 + i] = v4.z * 0.125f;
            qst[(c4 + 3) * 68 + i] = v4.w * 0.125f;
        }
    }

    float mrow[4], lrow[4], o[4][4];
    #pragma unroll
    for (int r = 0; r < 4; ++r) {
        mrow[r] = -1e30f;
        lrow[r] = 0.f;
        #pragma unroll
        for (int c = 0; c < 4; ++c) o[r][c] = 0.f;
    }

    for (int ck = 0; ck < 16; ++ck) {
        __syncthreads();   // protect ps/vs/kst from previous iteration readers
        // load K chunk (transposed) + V chunk (row-major)
        {
            const int row = tid >> 4;
            const int c4  = (tid & 15) * 4;
            #pragma unroll
            for (int it = 0; it < 4; ++it) {
                const int j = it * 16 + row;
                const int tok = (ck * 64 + j) * MM + m;
                float4 kv = *reinterpret_cast<const float4*>(
                    &K[headBase + (size_t)tok * DD + c4]);
                kst[(c4 + 0) * 68 + j] = kv.x;
                kst[(c4 + 1) * 68 + j] = kv.y;
                kst[(c4 + 2) * 68 + j] = kv.z;
                kst[(c4 + 3) * 68 + j] = kv.w;
                float4 vv = *reinterpret_cast<const float4*>(
                    &V[headBase + (size_t)tok * DD + c4]);
                *reinterpret_cast<float4*>(&vs[j * 68 + c4]) = vv;
            }
        }
        __syncthreads();

        // S = (Q*scale) @ K^T  -- 4x4 per thread
        float s[4][4];
        #pragma unroll
        for (int r = 0; r < 4; ++r)
            #pragma unroll
            for (int c = 0; c < 4; ++c) s[r][c] = 0.f;

        for (int d = 0; d < 64; ++d) {
            float4 qv = *reinterpret_cast<const float4*>(&qst[d * 68 + ty * 4]);
            float4 kv = *reinterpret_cast<const float4*>(&kst[d * 68 + tx * 4]);
            float qa[4] = {qv.x, qv.y, qv.z, qv.w};
            float ka[4] = {kv.x, kv.y, kv.z, kv.w};
            #pragma unroll
            for (int r = 0; r < 4; ++r)
                #pragma unroll
                for (int c = 0; c < 4; ++c)
                    s[r][c] += qa[r] * ka[c];
        }

        // online softmax update (rows reduce over the 16 lanes sharing ty)
        #pragma unroll
        for (int r = 0; r < 4; ++r) {
            float mx = fmaxf(fmaxf(s[r][0], s[r][1]), fmaxf(s[r][2], s[r][3]));
            #pragma unroll
            for (int off = 1; off < 16; off <<= 1)
                mx = fmaxf(mx, __shfl_xor_sync(0xffffffffu, mx, off));
            const float mnew  = fmaxf(mrow[r], mx);
            const float alpha = __expf(mrow[r] - mnew);
            float psum = 0.f;
            #pragma unroll
            for (int c = 0; c < 4; ++c) {
                s[r][c] = __expf(s[r][c] - mnew);
                psum += s[r][c];
            }
            #pragma unroll
            for (int off = 1; off < 16; off <<= 1)
                psum += __shfl_xor_sync(0xffffffffu, psum, off);
            lrow[r] = lrow[r] * alpha + psum;
            mrow[r] = mnew;
            #pragma unroll
            for (int c = 0; c < 4; ++c) o[r][c] *= alpha;
            *reinterpret_cast<float4*>(&ps[(ty * 4 + r) * 68 + tx * 4]) =
                make_float4(s[r][0], s[r][1], s[r][2], s[r][3]);
        }
        __syncthreads();

        // O += P @ V   (thread tile: rows ty*4+r, cols tx*4+c)
        for (int j = 0; j < 64; ++j) {
            float4 vv = *reinterpret_cast<const float4*>(&vs[j * 68 + tx * 4]);
            float va[4] = {vv.x, vv.y, vv.z, vv.w};
            #pragma unroll
            for (int r = 0; r < 4; ++r) {
                const float p = ps[(ty * 4 + r) * 68 + j];
                #pragma unroll
                for (int c = 0; c < 4; ++c)
                    o[r][c] += p * va[c];
            }
        }
    }

    // epilogue: normalize and scatter back to strided token positions
    #pragma unroll
    for (int r = 0; r < 4; ++r) {
        const float inv = 1.0f / lrow[r];
        const int i = ty * 4 + r;
        const int tok = (qb * 64 + i) * MM + m;
        float4 ov = make_float4(o[r][0] * inv, o[r][1] * inv,
                                o[r][2] * inv, o[r][3] * inv);
        *reinterpret_cast<float4*>(&O[headBase + (size_t)tok * DD + tx * 4]) = ov;
    }
}

// ---------------------------------------------------------------------------
extern "C" void kernel_launch(void* const* d_in, const int* in_sizes, int n_in,
                              void* d_out, int out_size)
{
    const float* x  = (const float*)d_in[0];
    const float* Wq = (const float*)d_in[1];
    const float* bq = (const float*)d_in[2];
    const float* Wk = (const float*)d_in[3];
    const float* bk = (const float*)d_in[4];
    const float* Wv = (const float*)d_in[5];
    const float* bv = (const float*)d_in[6];
    const float* Wo = (const float*)d_in[7];
    const float* bo = (const float*)d_in[8];
    float* out = (float*)d_out;

    float *Qp, *Kp, *Vp, *Op;
    cudaGetSymbolAddress((void**)&Qp, g_Q);
    cudaGetSymbolAddress((void**)&Kp, g_K);
    cudaGetSymbolAddress((void**)&Vp, g_V);
    cudaGetSymbolAddress((void**)&Op, g_O);

    const dim3 gemmGrid(DD / 128, NTOK / 128);
    const dim3 gemmBlk(256);

    // Q/K/V projections
    sgemm_bias<<<gemmGrid, gemmBlk>>>(x, Wq, bq, Qp, NTOK, DD, DD);
    sgemm_bias<<<gemmGrid, gemmBlk>>>(x, Wk, bk, Kp, NTOK, DD, DD);
    sgemm_bias<<<gemmGrid, gemmBlk>>>(x, Wv, bv, Vp, NTOK, DD, DD);

    // attention over 256 slices x 16 q-blocks
    const int smemBytes = 4 * 64 * 68 * (int)sizeof(float);  // 69632
    cudaFuncSetAttribute(attn_kernel,
                         cudaFuncAttributeMaxDynamicSharedMemorySize, smemBytes);
    attn_kernel<<<dim3(16, BB * HH * MM), 256, smemBytes>>>(Qp, Kp, Vp, Op);

    // output projection
    sgemm_bias<<<gemmGrid, gemmBlk>>>(Op, Wo, bo, out, NTOK, DD, DD);
}

// round 3
// speedup vs baseline: 1.6144x; 1.6144x over previous
#include <cuda_runtime.h>
#include <cuda_bf16.h>
#include <cstdint>

// Problem constants
#define BB 4
#define LL 4096
#define DD 1024
#define HH 16
#define MM 4
#define DK 64
#define NTOK (BB * LL)          // 16384

// ---------------- scratch (__device__ globals; no cudaMalloc allowed) -------
__device__ float g_Q[(size_t)NTOK * DD];
__device__ float g_K[(size_t)NTOK * DD];
__device__ float g_V[(size_t)NTOK * DD];
__device__ float g_O[(size_t)NTOK * DD];
__device__ __nv_bfloat16 g_xh[(size_t)NTOK * DD];
__device__ __nv_bfloat16 g_xl[(size_t)NTOK * DD];
__device__ __nv_bfloat16 g_Oh[(size_t)NTOK * DD];
__device__ __nv_bfloat16 g_Ol[(size_t)NTOK * DD];
__device__ __nv_bfloat16 g_Wth[4 * DD * DD];   // W^T hi (N-major: [n][k])
__device__ __nv_bfloat16 g_Wtl[4 * DD * DD];   // W^T lo

// ---------------- PTX helpers (sm_80-level only: no tcgen05) ----------------
__device__ __forceinline__ uint32_t smem_u32(const void* p) {
    uint32_t a;
    asm("{ .reg .u64 t; cvta.to.shared.u64 t, %1; cvt.u32.u64 %0, t; }"
        : "=r"(a) : "l"(p));
    return a;
}
#define CP_ASYNC16(dst, src) \
    asm volatile("cp.async.cg.shared.global [%0], [%1], 16;" \
                 :: "r"(dst), "l"(src) : "memory")
#define CP_COMMIT() asm volatile("cp.async.commit_group;" ::: "memory")
#define CP_WAIT1()  asm volatile("cp.async.wait_group 1;" ::: "memory")
#define CP_WAIT0()  asm volatile("cp.async.wait_group 0;" ::: "memory")

#define LDMATRIX_X4(r0, r1, r2, r3, addr)                                     \
    asm volatile("ldmatrix.sync.aligned.m8n8.x4.shared.b16 {%0,%1,%2,%3}, [%4];" \
                 : "=r"(r0), "=r"(r1), "=r"(r2), "=r"(r3) : "r"(addr))

#define MMA16816(c, a, b)                                                     \
    asm volatile("mma.sync.aligned.m16n8k16.row.col.f32.bf16.bf16.f32 "       \
                 "{%0,%1,%2,%3}, {%4,%5,%6,%7}, {%8,%9}, {%0,%1,%2,%3};"      \
                 : "+f"((c)[0]), "+f"((c)[1]), "+f"((c)[2]), "+f"((c)[3])     \
                 : "r"((a)[0]), "r"((a)[1]), "r"((a)[2]), "r"((a)[3]),        \
                   "r"((b)[0]), "r"((b)[1]))

// ---------------- conversion kernels ----------------------------------------
__global__ __launch_bounds__(256) void cvt_split(
    const float* __restrict__ X, __nv_bfloat16* __restrict__ Hh,
    __nv_bfloat16* __restrict__ Ll)
{
    size_t i = ((size_t)blockIdx.x * 256 + threadIdx.x) * 4;
    float4 v = *reinterpret_cast<const float4*>(X + i);
    __nv_bfloat16 h[4], l[4];
    float f[4] = {v.x, v.y, v.z, v.w};
    #pragma unroll
    for (int j = 0; j < 4; ++j) {
        h[j] = __float2bfloat16(f[j]);
        l[j] = __float2bfloat16(f[j] - __bfloat162float(h[j]));
    }
    *reinterpret_cast<uint2*>(Hh + i) = *reinterpret_cast<uint2*>(h);
    *reinterpret_cast<uint2*>(Ll + i) = *reinterpret_cast<uint2*>(l);
}

// transpose + split:  Wt[n][k] = W[k][n]
__global__ __launch_bounds__(256) void cvt_w(
    const float* __restrict__ W, __nv_bfloat16* __restrict__ Th,
    __nv_bfloat16* __restrict__ Tl)
{
    __shared__ float t[32][33];
    const int k0 = blockIdx.y * 32, n0 = blockIdx.x * 32;
    const int tx = threadIdx.x, ty = threadIdx.y;   // 32 x 8
    #pragma unroll
    for (int j = 0; j < 4; ++j)
        t[ty + 8 * j][tx] = W[(size_t)(k0 + ty + 8 * j) * DD + n0 + tx];
    __syncthreads();
    #pragma unroll
    for (int j = 0; j < 4; ++j) {
        const int n = ty + 8 * j;
        float w = t[tx][n];
        __nv_bfloat16 h = __float2bfloat16(w);
        __nv_bfloat16 l = __float2bfloat16(w - __bfloat162float(h));
        Th[(size_t)(n0 + n) * DD + k0 + tx] = h;
        Tl[(size_t)(n0 + n) * DD + k0 + tx] = l;
    }
}

// ---------------- mma.sync split-bf16 GEMM -----------------------------------
// C[16384,1024] = (Ah+Al)[M,K] @ (Bh+Bl)^T + bias, B stored N-major [n][k].
// CTA 128x128, K-chunk 64, 8 warps (2x4), warp tile 64x32, double buffer.
#define GKC   64
#define NCH   (DD / GKC)        // 16
#define PITCH 72                // elems per smem row (pad 64 -> 72)
#define PITCHB (PITCH * 2)      // 144 bytes (9 x 16B chunks, coprime w/ 8)
#define TILEB (128 * PITCHB)    // 18432 bytes per tile
#define STAGEB (4 * TILEB)      // Ah, Al, Bh, Bl

__device__ __forceinline__ void g_load_chunk(
    uint32_t sb, int s,
    const __nv_bfloat16* __restrict__ Ah, const __nv_bfloat16* __restrict__ Al,
    const __nv_bfloat16* __restrict__ Bh, const __nv_bfloat16* __restrict__ Bl,
    int M0, int N0, int ck, int tid)
{
    const __nv_bfloat16* bases[4] = {Ah, Al, Bh, Bl};
    const int r0s[4] = {M0, M0, N0, N0};
    #pragma unroll
    for (int t = 0; t < 4; ++t) {
        const __nv_bfloat16* base = bases[t];
        const int r0 = r0s[t];
        const uint32_t tb = sb + (uint32_t)s * STAGEB + (uint32_t)t * TILEB;
        #pragma unroll
        for (int i = 0; i < 4; ++i) {
            const int idx = i * 256 + tid;          // 0..1023
            const int row = idx >> 3, c = idx & 7;
            const void* g = base + (size_t)(r0 + row) * DD + ck * GKC + c * 8;
            CP_ASYNC16(tb + row * PITCHB + c * 16, g);
        }
    }
    CP_COMMIT();
}

__global__ __launch_bounds__(256) void gemm_mma(
    const __nv_bfloat16* __restrict__ Ah, const __nv_bfloat16* __restrict__ Al,
    const __nv_bfloat16* __restrict__ Bh, const __nv_bfloat16* __restrict__ Bl,
    const float* __restrict__ bias, float* __restrict__ C)
{
    extern __shared__ char smem[];
    const uint32_t sb = smem_u32(smem);
    const int tid = threadIdx.x;
    const int wid = tid >> 5, l = tid & 31;
    const int wm = (wid >> 2) * 64;      // warp M offset in CTA tile
    const int wn = (wid & 3) * 32;       // warp N offset
    const int M0 = blockIdx.y * 128, N0 = blockIdx.x * 128;

    float c[4][4][4];
    #pragma unroll
    for (int mf = 0; mf < 4; ++mf)
        #pragma unroll
        for (int nf = 0; nf < 4; ++nf)
            #pragma unroll
            for (int e = 0; e < 4; ++e) c[mf][nf][e] = 0.f;

    // per-lane ldmatrix base offsets (within a tile)
    const uint32_t offA = (uint32_t)(wm + (l & 15)) * PITCHB + ((l >> 4) << 4);
    const uint32_t offB = (uint32_t)(wn + (l & 7) + ((l >> 4) << 3)) * PITCHB
                        + (((l >> 3) & 1) << 4);

    g_load_chunk(sb, 0, Ah, Al, Bh, Bl, M0, N0, 0, tid);
    g_load_chunk(sb, 1, Ah, Al, Bh, Bl, M0, N0, 1, tid);

    for (int ck = 0; ck < NCH; ++ck) {
        const int s = ck & 1;
        if (ck == NCH - 1) CP_WAIT0(); else CP_WAIT1();
        __syncthreads();

        const uint32_t stg = sb + (uint32_t)s * STAGEB;
        const uint32_t aH = stg + offA;
        const uint32_t aL = stg + TILEB + offA;
        const uint32_t bH = stg + 2 * TILEB + offB;
        const uint32_t bL = stg + 3 * TILEB + offB;

        #pragma unroll
        for (int ks = 0; ks < 4; ++ks) {
            const uint32_t kb = (uint32_t)ks * 32;
            uint32_t ah[4][4], al[4][4], bh[4][2], bl[4][2];
            #pragma unroll
            for (int mf = 0; mf < 4; ++mf) {
                const uint32_t d = (uint32_t)(mf * 16) * PITCHB + kb;
                LDMATRIX_X4(ah[mf][0], ah[mf][1], ah[mf][2], ah[mf][3], aH + d);
                LDMATRIX_X4(al[mf][0], al[mf][1], al[mf][2], al[mf][3], aL + d);
            }
            #pragma unroll
            for (int nh = 0; nh < 2; ++nh) {
                const uint32_t d = (uint32_t)(nh * 16) * PITCHB + kb;
                LDMATRIX_X4(bh[nh * 2][0], bh[nh * 2][1],
                            bh[nh * 2 + 1][0], bh[nh * 2 + 1][1], bH + d);
                LDMATRIX_X4(bl[nh * 2][0], bl[nh * 2][1],
                            bl[nh * 2 + 1][0], bl[nh * 2 + 1][1], bL + d);
            }
            #pragma unroll
            for (int mf = 0; mf < 4; ++mf)
                #pragma unroll
                for (int nf = 0; nf < 4; ++nf) {
                    MMA16816(c[mf][nf], ah[mf], bh[nf]);
                    MMA16816(c[mf][nf], ah[mf], bl[nf]);
                    MMA16816(c[mf][nf], al[mf], bh[nf]);
                }
        }
        __syncthreads();
        if (ck + 2 < NCH)
            g_load_chunk(sb, s, Ah, Al, Bh, Bl, M0, N0, ck + 2, tid);
    }

    // epilogue: registers -> global (+bias), float2 stores
    #pragma unroll
    for (int mf = 0; mf < 4; ++mf) {
        const int r0 = M0 + wm + mf * 16 + (l >> 2);
        #pragma unroll
        for (int nf = 0; nf < 4; ++nf) {
            const int col = N0 + wn + nf * 8 + (l & 3) * 2;
            const float2 bi = *reinterpret_cast<const float2*>(bias + col);
            float2 v0 = {c[mf][nf][0] + bi.x, c[mf][nf][1] + bi.y};
            float2 v1 = {c[mf][nf][2] + bi.x, c[mf][nf][3] + bi.y};
            *reinterpret_cast<float2*>(C + (size_t)r0 * DD + col) = v0;
            *reinterpret_cast<float2*>(C + (size_t)(r0 + 8) * DD + col) = v1;
        }
    }
}

// ---------------- fp32 flash attention (unchanged from R1) ------------------
__global__ __launch_bounds__(256) void attn_kernel(
    const float* __restrict__ Q, const float* __restrict__ K,
    const float* __restrict__ V, float* __restrict__ O)
{
    extern __shared__ float sm[];
    float* qst = sm;
    float* kst = sm + 64 * 68;
    float* vs  = sm + 2 * 64 * 68;
    float* ps  = sm + 3 * 64 * 68;

    int sl = blockIdx.y;
    const int m = sl & 3;
    const int h = (sl >> 2) & 15;
    const int b = sl >> 6;
    const int qb = blockIdx.x;
    const int tid = threadIdx.x;
    const int ty = tid >> 4;
    const int tx = tid & 15;

    const size_t headBase = ((size_t)b * LL) * DD + (size_t)h * DK;

    {
        const int row = tid >> 4;
        const int c4  = (tid & 15) * 4;
        #pragma unroll
        for (int it = 0; it < 4; ++it) {
            const int i = it * 16 + row;
            const int tok = (qb * 64 + i) * MM + m;
            float4 v4 = *reinterpret_cast<const float4*>(
                &Q[headBase + (size_t)tok * DD + c4]);
            qst[(c4 + 0) * 68 + i] = v4.x * 0.125f;
            qst[(c4 + 1) * 68 + i] = v4.y * 0.125f;
            qst[(c4 + 2) * 68 + i] = v4.z * 0.125f;
            qst[(c4 + 3) * 68 + i] = v4.w * 0.125f;
        }
    }

    float mrow[4], lrow[4], o[4][4];
    #pragma unroll
    for (int r = 0; r < 4; ++r) {
        mrow[r] = -1e30f;
        lrow[r] = 0.f;
        #pragma unroll
        for (int c = 0; c < 4; ++c) o[r][c] = 0.f;
    }

    for (int ck = 0; ck < 16; ++ck) {
        __syncthreads();
        {
            const int row = tid >> 4;
            const int c4  = (tid & 15) * 4;
            #pragma unroll
            for (int it = 0; it < 4; ++it) {
                const int j = it * 16 + row;
                const int tok = (ck * 64 + j) * MM + m;
                float4 kv = *reinterpret_cast<const float4*>(
                    &K[headBase + (size_t)tok * DD + c4]);
                kst[(c4 + 0) * 68 + j] = kv.x;
                kst[(c4 + 1) * 68 + j] = kv.y;
                kst[(c4 + 2) * 68 + j] = kv.z;
                kst[(c4 + 3) * 68 + j] = kv.w;
                float4 vv = *reinterpret_cast<const float4*>(
                    &V[headBase + (size_t)tok * DD + c4]);
                *reinterpret_cast<float4*>(&vs[j * 68 + c4]) = vv;
            }
        }
        __syncthreads();

        float s[4][4];
        #pragma unroll
        for (int r = 0; r < 4; ++r)
            #pragma unroll
            for (int c = 0; c < 4; ++c) s[r][c] = 0.f;

        for (int d = 0; d < 64; ++d) {
            float4 qv = *reinterpret_cast<const float4*>(&qst[d * 68 + ty * 4]);
            float4 kv = *reinterpret_cast<const float4*>(&kst[d * 68 + tx * 4]);
            float qa[4] = {qv.x, qv.y, qv.z, qv.w};
            float ka[4] = {kv.x, kv.y, kv.z, kv.w};
            #pragma unroll
            for (int r = 0; r < 4; ++r)
                #pragma unroll
                for (int c = 0; c < 4; ++c)
                    s[r][c] += qa[r] * ka[c];
        }

        #pragma unroll
        for (int r = 0; r < 4; ++r) {
            float mx = fmaxf(fmaxf(s[r][0], s[r][1]), fmaxf(s[r][2], s[r][3]));
            #pragma unroll
            for (int off = 1; off < 16; off <<= 1)
                mx = fmaxf(mx, __shfl_xor_sync(0xffffffffu, mx, off));
            const float mnew  = fmaxf(mrow[r], mx);
            const float alpha = __expf(mrow[r] - mnew);
            float psum = 0.f;
            #pragma unroll
            for (int c = 0; c < 4; ++c) {
                s[r][c] = __expf(s[r][c] - mnew);
                psum += s[r][c];
            }
            #pragma unroll
            for (int off = 1; off < 16; off <<= 1)
                psum += __shfl_xor_sync(0xffffffffu, psum, off);
            lrow[r] = lrow[r] * alpha + psum;
            mrow[r] = mnew;
            #pragma unroll
            for (int c = 0; c < 4; ++c) o[r][c] *= alpha;
            *reinterpret_cast<float4*>(&ps[(ty * 4 + r) * 68 + tx * 4]) =
                make_float4(s[r][0], s[r][1], s[r][2], s[r][3]);
        }
        __syncthreads();

        for (int j = 0; j < 64; ++j) {
            float4 vv = *reinterpret_cast<const float4*>(&vs[j * 68 + tx * 4]);
            float va[4] = {vv.x, vv.y, vv.z, vv.w};
            #pragma unroll
            for (int r = 0; r < 4; ++r) {
                const float p = ps[(ty * 4 + r) * 68 + j];
                #pragma unroll
                for (int c = 0; c < 4; ++c)
                    o[r][c] += p * va[c];
            }
        }
    }

    #pragma unroll
    for (int r = 0; r < 4; ++r) {
        const float inv = 1.0f / lrow[r];
        const int i = ty * 4 + r;
        const int tok = (qb * 64 + i) * MM + m;
        float4 ov = make_float4(o[r][0] * inv, o[r][1] * inv,
                                o[r][2] * inv, o[r][3] * inv);
        *reinterpret_cast<float4*>(&O[headBase + (size_t)tok * DD + tx * 4]) = ov;
    }
}

// ---------------------------------------------------------------------------
extern "C" void kernel_launch(void* const* d_in, const int* in_sizes, int n_in,
                              void* d_out, int out_size)
{
    const float* x  = (const float*)d_in[0];
    const float* Wq = (const float*)d_in[1];
    const float* bq = (const float*)d_in[2];
    const float* Wk = (const float*)d_in[3];
    const float* bk = (const float*)d_in[4];
    const float* Wv = (const float*)d_in[5];
    const float* bv = (const float*)d_in[6];
    const float* Wo = (const float*)d_in[7];
    const float* bo = (const float*)d_in[8];
    float* out = (float*)d_out;

    float *Qp, *Kp, *Vp, *Op;
    cudaGetSymbolAddress((void**)&Qp, g_Q);
    cudaGetSymbolAddress((void**)&Kp, g_K);
    cudaGetSymbolAddress((void**)&Vp, g_V);
    cudaGetSymbolAddress((void**)&Op, g_O);
    __nv_bfloat16 *xh, *xl, *Oh, *Ol, *Wth, *Wtl;
    cudaGetSymbolAddress((void**)&xh, g_xh);
    cudaGetSymbolAddress((void**)&xl, g_xl);
    cudaGetSymbolAddress((void**)&Oh, g_Oh);
    cudaGetSymbolAddress((void**)&Ol, g_Ol);
    cudaGetSymbolAddress((void**)&Wth, g_Wth);
    cudaGetSymbolAddress((void**)&Wtl, g_Wtl);

    // conversions
    const int cvtBlocks = (NTOK * DD) / (256 * 4);
    cvt_split<<<cvtBlocks, 256>>>(x, xh, xl);
    const dim3 wGrid(DD / 32, DD / 32);
    const dim3 wBlk(32, 8);
    cvt_w<<<wGrid, wBlk>>>(Wq, Wth + 0 * DD * DD, Wtl + 0 * DD * DD);
    cvt_w<<<wGrid, wBlk>>>(Wk, Wth + 1 * DD * DD, Wtl + 1 * DD * DD);
    cvt_w<<<wGrid, wBlk>>>(Wv, Wth + 2 * DD * DD, Wtl + 2 * DD * DD);
    cvt_w<<<wGrid, wBlk>>>(Wo, Wth + 3 * DD * DD, Wtl + 3 * DD * DD);

    // mma.sync GEMMs
    const int gemmSmem = 2 * STAGEB;   // 147456 B
    cudaFuncSetAttribute(gemm_mma, cudaFuncAttributeMaxDynamicSharedMemorySize,
                         gemmSmem);
    const dim3 gGrid(DD / 128, NTOK / 128);
    gemm_mma<<<gGrid, 256, gemmSmem>>>(xh, xl, Wth + 0 * DD * DD, Wtl + 0 * DD * DD, bq, Qp);
    gemm_mma<<<gGrid, 256, gemmSmem>>>(xh, xl, Wth + 1 * DD * DD, Wtl + 1 * DD * DD, bk, Kp);
    gemm_mma<<<gGrid, 256, gemmSmem>>>(xh, xl, Wth + 2 * DD * DD, Wtl + 2 * DD * DD, bv, Vp);

    // attention (fp32)
    const int attnSmem = 4 * 64 * 68 * (int)sizeof(float);
    cudaFuncSetAttribute(attn_kernel,
                         cudaFuncAttributeMaxDynamicSharedMemorySize, attnSmem);
    attn_kernel<<<dim3(16, BB * HH * MM), 256, attnSmem>>>(Qp, Kp, Vp, Op);

    // output projection
    cvt_split<<<cvtBlocks, 256>>>(Op, Oh, Ol);
    gemm_mma<<<gGrid, 256, gemmSmem>>>(Oh, Ol, Wth + 3 * DD * DD, Wtl + 3 * DD * DD, bo, out);
}

// round 4
// speedup vs baseline: 2.7322x; 1.6923x over previous
#include <cuda_runtime.h>
#include <cuda_bf16.h>
#include <cstdint>

// Problem constants
#define BB 4
#define LL 4096
#define DD 1024
#define HH 16
#define MM 4
#define DK 64
#define NTOK (BB * LL)          // 16384
#define NSLICE (BB * HH * MM)   // 256
#define NJ (LL / MM)            // 1024 tokens per slice

// ---------------- scratch (__device__ globals; no cudaMalloc allowed) -------
__device__ float g_Q[(size_t)NTOK * DD];
__device__ float g_K[(size_t)NTOK * DD];
__device__ float g_V[(size_t)NTOK * DD];
__device__ __nv_bfloat16 g_xh[(size_t)NTOK * DD];
__device__ __nv_bfloat16 g_xl[(size_t)NTOK * DD];
__device__ __nv_bfloat16 g_Qh[(size_t)NTOK * DD];
__device__ __nv_bfloat16 g_Ql[(size_t)NTOK * DD];
__device__ __nv_bfloat16 g_Kh[(size_t)NTOK * DD];
__device__ __nv_bfloat16 g_Kl[(size_t)NTOK * DD];
__device__ __nv_bfloat16 g_Vth[(size_t)NSLICE * DK * NJ];  // [slice][d][j]
__device__ __nv_bfloat16 g_Vtl[(size_t)NSLICE * DK * NJ];
__device__ __nv_bfloat16 g_Oh[(size_t)NTOK * DD];
__device__ __nv_bfloat16 g_Ol[(size_t)NTOK * DD];
__device__ __nv_bfloat16 g_Wth[4 * DD * DD];   // W^T hi (N-major: [n][k])
__device__ __nv_bfloat16 g_Wtl[4 * DD * DD];   // W^T lo

// ---------------- PTX helpers (sm_80-level only) ----------------------------
__device__ __forceinline__ uint32_t smem_u32(const void* p) {
    uint32_t a;
    asm("{ .reg .u64 t; cvta.to.shared.u64 t, %1; cvt.u32.u64 %0, t; }"
        : "=r"(a) : "l"(p));
    return a;
}
#define CP_ASYNC16(dst, src) \
    asm volatile("cp.async.cg.shared.global [%0], [%1], 16;" \
                 :: "r"(dst), "l"(src) : "memory")
#define CP_COMMIT() asm volatile("cp.async.commit_group;" ::: "memory")
#define CP_WAIT1()  asm volatile("cp.async.wait_group 1;" ::: "memory")
#define CP_WAIT0()  asm volatile("cp.async.wait_group 0;" ::: "memory")

#define LDMATRIX_X4(r0, r1, r2, r3, addr)                                     \
    asm volatile("ldmatrix.sync.aligned.m8n8.x4.shared.b16 {%0,%1,%2,%3}, [%4];" \
                 : "=r"(r0), "=r"(r1), "=r"(r2), "=r"(r3) : "r"(addr))

#define MMA16816(c, a, b)                                                     \
    asm volatile("mma.sync.aligned.m16n8k16.row.col.f32.bf16.bf16.f32 "       \
                 "{%0,%1,%2,%3}, {%4,%5,%6,%7}, {%8,%9}, {%0,%1,%2,%3};"      \
                 : "+f"((c)[0]), "+f"((c)[1]), "+f"((c)[2]), "+f"((c)[3])     \
                 : "r"((a)[0]), "r"((a)[1]), "r"((a)[2]), "r"((a)[3]),        \
                   "r"((b)[0]), "r"((b)[1]))

__device__ __forceinline__ uint32_t pack_bf16(float lo, float hi) {
    uint32_t r;
    asm("cvt.rn.bf16x2.f32 %0, %1, %2;" : "=r"(r) : "f"(hi), "f"(lo));
    return r;
}

// ---------------- conversion kernels ----------------------------------------
__global__ __launch_bounds__(256) void cvt_split(
    const float* __restrict__ X, __nv_bfloat16* __restrict__ Hh,
    __nv_bfloat16* __restrict__ Ll, float scale)
{
    size_t i = ((size_t)blockIdx.x * 256 + threadIdx.x) * 4;
    float4 v = *reinterpret_cast<const float4*>(X + i);
    __nv_bfloat16 h[4], l[4];
    float f[4] = {v.x * scale, v.y * scale, v.z * scale, v.w * scale};
    #pragma unroll
    for (int j = 0; j < 4; ++j) {
        h[j] = __float2bfloat16(f[j]);
        l[j] = __float2bfloat16(f[j] - __bfloat162float(h[j]));
    }
    *reinterpret_cast<uint2*>(Hh + i) = *reinterpret_cast<uint2*>(h);
    *reinterpret_cast<uint2*>(Ll + i) = *reinterpret_cast<uint2*>(l);
}

// transpose + split:  Wt[n][k] = W[k][n]
__global__ __launch_bounds__(256) void cvt_w(
    const float* __restrict__ W, __nv_bfloat16* __restrict__ Th,
    __nv_bfloat16* __restrict__ Tl)
{
    __shared__ float t[32][33];
    const int k0 = blockIdx.y * 32, n0 = blockIdx.x * 32;
    const int tx = threadIdx.x, ty = threadIdx.y;   // 32 x 8
    #pragma unroll
    for (int j = 0; j < 4; ++j)
        t[ty + 8 * j][tx] = W[(size_t)(k0 + ty + 8 * j) * DD + n0 + tx];
    __syncthreads();
    #pragma unroll
    for (int j = 0; j < 4; ++j) {
        const int n = ty + 8 * j;
        float w = t[tx][n];
        __nv_bfloat16 h = __float2bfloat16(w);
        __nv_bfloat16 l = __float2bfloat16(w - __bfloat162float(h));
        Th[(size_t)(n0 + n) * DD + k0 + tx] = h;
        Tl[(size_t)(n0 + n) * DD + k0 + tx] = l;
    }
}

// V transpose per slice: V fp32 [tok][h*64+d] -> Vt [slice][d][j] bf16 hi/lo
__global__ __launch_bounds__(256) void v_cvt(
    const float* __restrict__ V, __nv_bfloat16* __restrict__ Vth,
    __nv_bfloat16* __restrict__ Vtl)
{
    __shared__ float t[64][65];
    const int jb = blockIdx.x;      // 16 blocks of 64 j
    const int sl = blockIdx.y;      // 256 slices
    const int m = sl & 3, h = (sl >> 2) & 15, b = sl >> 6;
    const size_t base = ((size_t)b * LL) * DD + (size_t)h * DK;
    const int tid = threadIdx.x;
    {
        const int jj = tid >> 2;           // 0..63
        const int d0 = (tid & 3) * 16;     // 16 d per thread
        const int tok = (jb * 64 + jj) * MM + m;
        const float* src = V + base + (size_t)tok * DD + d0;
        #pragma unroll
        for (int i = 0; i < 4; ++i) {
            float4 v4 = *reinterpret_cast<const float4*>(src + i * 4);
            t[jj][d0 + i * 4 + 0] = v4.x;
            t[jj][d0 + i * 4 + 1] = v4.y;
            t[jj][d0 + i * 4 + 2] = v4.z;
            t[jj][d0 + i * 4 + 3] = v4.w;
        }
    }
    __syncthreads();
    {
        const int d  = tid >> 2;           // 0..63
        const int j0 = (tid & 3) * 16;     // 16 j per thread
        const size_t dst = ((size_t)sl * DK + d) * NJ + jb * 64 + j0;
        #pragma unroll
        for (int i = 0; i < 16; i += 4) {
            float f[4];
            #pragma unroll
            for (int u = 0; u < 4; ++u) f[u] = t[j0 + i + u][d];
            __nv_bfloat16 hh[4], ll[4];
            #pragma unroll
            for (int u = 0; u < 4; ++u) {
                hh[u] = __float2bfloat16(f[u]);
                ll[u] = __float2bfloat16(f[u] - __bfloat162float(hh[u]));
            }
            *reinterpret_cast<uint2*>(Vth + dst + i) = *reinterpret_cast<uint2*>(hh);
            *reinterpret_cast<uint2*>(Vtl + dst + i) = *reinterpret_cast<uint2*>(ll);
        }
    }
}

// ---------------- mma.sync split-bf16 GEMM (as R3) --------------------------
#define GKC   64
#define NCH   (DD / GKC)        // 16
#define PITCH 72
#define PITCHB (PITCH * 2)      // 144 B
#define TILEB (128 * PITCHB)    // 18432
#define STAGEB (4 * TILEB)

__device__ __forceinline__ void g_load_chunk(
    uint32_t sb, int s,
    const __nv_bfloat16* __restrict__ Ah, const __nv_bfloat16* __restrict__ Al,
    const __nv_bfloat16* __restrict__ Bh, const __nv_bfloat16* __restrict__ Bl,
    int M0, int N0, int ck, int tid)
{
    const __nv_bfloat16* bases[4] = {Ah, Al, Bh, Bl};
    const int r0s[4] = {M0, M0, N0, N0};
    #pragma unroll
    for (int t = 0; t < 4; ++t) {
        const __nv_bfloat16* base = bases[t];
        const int r0 = r0s[t];
        const uint32_t tb = sb + (uint32_t)s * STAGEB + (uint32_t)t * TILEB;
        #pragma unroll
        for (int i = 0; i < 4; ++i) {
            const int idx = i * 256 + tid;
            const int row = idx >> 3, c = idx & 7;
            const void* g = base + (size_t)(r0 + row) * DD + ck * GKC + c * 8;
            CP_ASYNC16(tb + row * PITCHB + c * 16, g);
        }
    }
    CP_COMMIT();
}

__global__ __launch_bounds__(256) void gemm_mma(
    const __nv_bfloat16* __restrict__ Ah, const __nv_bfloat16* __restrict__ Al,
    const __nv_bfloat16* __restrict__ Bh, const __nv_bfloat16* __restrict__ Bl,
    const float* __restrict__ bias, float* __restrict__ C)
{
    extern __shared__ char smem[];
    const uint32_t sb = smem_u32(smem);
    const int tid = threadIdx.x;
    const int wid = tid >> 5, l = tid & 31;
    const int wm = (wid >> 2) * 64;
    const int wn = (wid & 3) * 32;
    const int M0 = blockIdx.y * 128, N0 = blockIdx.x * 128;

    float c[4][4][4];
    #pragma unroll
    for (int mf = 0; mf < 4; ++mf)
        #pragma unroll
        for (int nf = 0; nf < 4; ++nf)
            #pragma unroll
            for (int e = 0; e < 4; ++e) c[mf][nf][e] = 0.f;

    const uint32_t offA = (uint32_t)(wm + (l & 15)) * PITCHB + ((l >> 4) << 4);
    const uint32_t offB = (uint32_t)(wn + (l & 7) + ((l >> 4) << 3)) * PITCHB
                        + (((l >> 3) & 1) << 4);

    g_load_chunk(sb, 0, Ah, Al, Bh, Bl, M0, N0, 0, tid);
    g_load_chunk(sb, 1, Ah, Al, Bh, Bl, M0, N0, 1, tid);

    for (int ck = 0; ck < NCH; ++ck) {
        const int s = ck & 1;
        if (ck == NCH - 1) CP_WAIT0(); else CP_WAIT1();
        __syncthreads();

        const uint32_t stg = sb + (uint32_t)s * STAGEB;
        const uint32_t aH = stg + offA;
        const uint32_t aL = stg + TILEB + offA;
        const uint32_t bH = stg + 2 * TILEB + offB;
        const uint32_t bL = stg + 3 * TILEB + offB;

        #pragma unroll
        for (int ks = 0; ks < 4; ++ks) {
            const uint32_t kb = (uint32_t)ks * 32;
            uint32_t ah[4][4], al[4][4], bh[4][2], bl[4][2];
            #pragma unroll
            for (int mf = 0; mf < 4; ++mf) {
                const uint32_t d = (uint32_t)(mf * 16) * PITCHB + kb;
                LDMATRIX_X4(ah[mf][0], ah[mf][1], ah[mf][2], ah[mf][3], aH + d);
                LDMATRIX_X4(al[mf][0], al[mf][1], al[mf][2], al[mf][3], aL + d);
            }
            #pragma unroll
            for (int nh = 0; nh < 2; ++nh) {
                const uint32_t d = (uint32_t)(nh * 16) * PITCHB + kb;
                LDMATRIX_X4(bh[nh * 2][0], bh[nh * 2][1],
                            bh[nh * 2 + 1][0], bh[nh * 2 + 1][1], bH + d);
                LDMATRIX_X4(bl[nh * 2][0], bl[nh * 2][1],
                            bl[nh * 2 + 1][0], bl[nh * 2 + 1][1], bL + d);
            }
            #pragma unroll
            for (int mf = 0; mf < 4; ++mf)
                #pragma unroll
                for (int nf = 0; nf < 4; ++nf) {
                    MMA16816(c[mf][nf], ah[mf], bh[nf]);
                    MMA16816(c[mf][nf], ah[mf], bl[nf]);
                    MMA16816(c[mf][nf], al[mf], bh[nf]);
                }
        }
        __syncthreads();
        if (ck + 2 < NCH)
            g_load_chunk(sb, s, Ah, Al, Bh, Bl, M0, N0, ck + 2, tid);
    }

    #pragma unroll
    for (int mf = 0; mf < 4; ++mf) {
        const int r0 = M0 + wm + mf * 16 + (l >> 2);
        #pragma unroll
        for (int nf = 0; nf < 4; ++nf) {
            const int col = N0 + wn + nf * 8 + (l & 3) * 2;
            const float2 bi = *reinterpret_cast<const float2*>(bias + col);
            float2 v0 = {c[mf][nf][0] + bi.x, c[mf][nf][1] + bi.y};
            float2 v1 = {c[mf][nf][2] + bi.x, c[mf][nf][3] + bi.y};
            *reinterpret_cast<float2*>(C + (size_t)r0 * DD + col) = v0;
            *reinterpret_cast<float2*>(C + (size_t)(r0 + 8) * DD + col) = v1;
        }
    }
}

// ---------------- tensor-core flash attention --------------------------------
// Grid: x = qblock (8 x 128 q rows), y = slice (256). 256 threads, 8 warps.
// Warp w owns q rows w*16..w*16+15 (softmax fully within warp).
#define APITCH 144               // K/Q tile row pitch bytes (64 bf16 + pad)
#define AQTILE (128 * APITCH)    // 18432
#define VPITCH 272               // Vt tile row pitch (128 bf16 + pad)
#define AVTILE (64 * VPITCH)     // 17408
#define KBASE (2 * AQTILE)
#define VBASE (6 * AQTILE)
#define ATT_SMEM (VBASE + 4 * AVTILE)   // 180224 B

__device__ __forceinline__ void attn_load_kv(
    uint32_t sb, int s, const __nv_bfloat16* __restrict__ Kh,
    const __nv_bfloat16* __restrict__ Kl, const __nv_bfloat16* __restrict__ Vth,
    const __nv_bfloat16* __restrict__ Vtl, size_t qkBase, size_t vBase,
    int m, int ck, int tid)
{
    const __nv_bfloat16* kb[2] = {Kh, Kl};
    #pragma unroll
    for (int t = 0; t < 2; ++t) {
        const uint32_t tile = sb + KBASE + (uint32_t)(s * 2 + t) * AQTILE;
        #pragma unroll
        for (int i = 0; i < 4; ++i) {
            const int idx = i * 256 + tid;
            const int row = idx >> 3, c = idx & 7;
            const int tok = (ck * 128 + row) * MM + m;
            const void* g = kb[t] + qkBase + (size_t)tok * DD + c * 8;
            CP_ASYNC16(tile + row * APITCH + c * 16, g);
        }
    }
    const __nv_bfloat16* vb[2] = {Vth, Vtl};
    #pragma unroll
    for (int t = 0; t < 2; ++t) {
        const uint32_t tile = sb + VBASE + (uint32_t)(s * 2 + t) * AVTILE;
        #pragma unroll
        for (int i = 0; i < 4; ++i) {
            const int idx = i * 256 + tid;
            const int row = idx >> 4, c = idx & 15;
            const void* g = vb[t] + vBase + (size_t)row * NJ + ck * 128 + c * 8;
            CP_ASYNC16(tile + row * VPITCH + c * 16, g);
        }
    }
    CP_COMMIT();
}

__global__ __launch_bounds__(256) void attn_mma(
    const __nv_bfloat16* __restrict__ Qh, const __nv_bfloat16* __restrict__ Ql,
    const __nv_bfloat16* __restrict__ Kh, const __nv_bfloat16* __restrict__ Kl,
    const __nv_bfloat16* __restrict__ Vth, const __nv_bfloat16* __restrict__ Vtl,
    __nv_bfloat16* __restrict__ Oh, __nv_bfloat16* __restrict__ Ol)
{
    extern __shared__ char smem[];
    const uint32_t sb = smem_u32(smem);
    const int tid = threadIdx.x, w = tid >> 5, l = tid & 31;
    const int qb = blockIdx.x;          // 0..7
    const int sl = blockIdx.y;          // 0..255
    const int m = sl & 3, h = (sl >> 2) & 15, b = sl >> 6;

    const size_t qkBase = ((size_t)b * LL) * DD + (size_t)h * DK;
    const size_t vBase  = (size_t)sl * DK * NJ;

    // Q tiles (hi, lo) loaded once (part of cp group 0)
    {
        const __nv_bfloat16* qB[2] = {Qh, Ql};
        #pragma unroll
        for (int t = 0; t < 2; ++t) {
            const uint32_t tile = sb + (uint32_t)t * AQTILE;
            #pragma unroll
            for (int i = 0; i < 4; ++i) {
                const int idx = i * 256 + tid;
                const int row = idx >> 3, c = idx & 7;
                const int tok = (qb * 128 + row) * MM + m;
                const void* g = qB[t] + qkBase + (size_t)tok * DD + c * 8;
                CP_ASYNC16(tile + row * APITCH + c * 16, g);
            }
        }
    }
    attn_load_kv(sb, 0, Kh, Kl, Vth, Vtl, qkBase, vBase, m, 0, tid);  // group 0
    attn_load_kv(sb, 1, Kh, Kl, Vth, Vtl, qkBase, vBase, m, 1, tid);  // group 1

    const uint32_t offA  = (uint32_t)(w * 16 + (l & 15)) * APITCH + ((l >> 4) << 4);
    const uint32_t offBk = (uint32_t)((l & 7) + ((l >> 4) << 3)) * APITCH
                         + (((l >> 3) & 1) << 4);
    const uint32_t offBv = (uint32_t)((l & 7) + ((l >> 4) << 3)) * VPITCH
                         + (((l >> 3) & 1) << 4);

    float o[8][4];
    #pragma unroll
    for (int nf = 0; nf < 8; ++nf)
        #pragma unroll
        for (int e = 0; e < 4; ++e) o[nf][e] = 0.f;
    float mrow0 = -1e30f, mrow1 = -1e30f, lsum0 = 0.f, lsum1 = 0.f;

    for (int ck = 0; ck < 8; ++ck) {
        const int s = ck & 1;
        if (ck == 7) CP_WAIT0(); else CP_WAIT1();
        __syncthreads();

        // ---- S = Q @ K^T (3-pass split) ----
        float c[16][4];
        #pragma unroll
        for (int nf = 0; nf < 16; ++nf)
            #pragma unroll
            for (int e = 0; e < 4; ++e) c[nf][e] = 0.f;

        const uint32_t qhA = sb + offA;
        const uint32_t qlA = sb + AQTILE + offA;
        const uint32_t khB = sb + KBASE + (uint32_t)(s * 2) * AQTILE + offBk;
        const uint32_t klB = khB + AQTILE;

        #pragma unroll
        for (int ks = 0; ks < 4; ++ks) {
            const uint32_t kb = (uint32_t)ks * 32;
            uint32_t ah[4], al[4];
            LDMATRIX_X4(ah[0], ah[1], ah[2], ah[3], qhA + kb);
            LDMATRIX_X4(al[0], al[1], al[2], al[3], qlA + kb);
            #pragma unroll
            for (int p = 0; p < 8; ++p) {
                const uint32_t d = (uint32_t)(p * 16) * APITCH + kb;
                uint32_t bh[4], bl[4];
                LDMATRIX_X4(bh[0], bh[1], bh[2], bh[3], khB + d);
                LDMATRIX_X4(bl[0], bl[1], bl[2], bl[3], klB + d);
                MMA16816(c[2 * p], ah, bh);
                MMA16816(c[2 * p], ah, bl);
                MMA16816(c[2 * p], al, bh);
                MMA16816(c[2 * p + 1], ah, bh + 2);
                MMA16816(c[2 * p + 1], ah, bl + 2);
                MMA16816(c[2 * p + 1], al, bh + 2);
            }
        }

        // ---- online softmax (rows within warp; quad lanes share a row) ----
        float mx0 = -1e30f, mx1 = -1e30f;
        #pragma unroll
        for (int nf = 0; nf < 16; ++nf) {
            mx0 = fmaxf(mx0, fmaxf(c[nf][0], c[nf][1]));
            mx1 = fmaxf(mx1, fmaxf(c[nf][2], c[nf][3]));
        }
        mx0 = fmaxf(mx0, __shfl_xor_sync(0xffffffffu, mx0, 1));
        mx0 = fmaxf(mx0, __shfl_xor_sync(0xffffffffu, mx0, 2));
        mx1 = fmaxf(mx1, __shfl_xor_sync(0xffffffffu, mx1, 1));
        mx1 = fmaxf(mx1, __shfl_xor_sync(0xffffffffu, mx1, 2));
        const float mn0 = fmaxf(mrow0, mx0), mn1 = fmaxf(mrow1, mx1);
        const float al0 = __expf(mrow0 - mn0), al1 = __expf(mrow1 - mn1);
        mrow0 = mn0; mrow1 = mn1;
        float s0 = 0.f, s1 = 0.f;
        #pragma unroll
        for (int nf = 0; nf < 16; ++nf) {
            c[nf][0] = __expf(c[nf][0] - mn0);
            c[nf][1] = __expf(c[nf][1] - mn0);
            c[nf][2] = __expf(c[nf][2] - mn1);
            c[nf][3] = __expf(c[nf][3] - mn1);
            s0 += c[nf][0] + c[nf][1];
            s1 += c[nf][2] + c[nf][3];
        }
        s0 += __shfl_xor_sync(0xffffffffu, s0, 1);
        s0 += __shfl_xor_sync(0xffffffffu, s0, 2);
        s1 += __shfl_xor_sync(0xffffffffu, s1, 1);
        s1 += __shfl_xor_sync(0xffffffffu, s1, 2);
        lsum0 = lsum0 * al0 + s0;
        lsum1 = lsum1 * al1 + s1;
        #pragma unroll
        for (int nf = 0; nf < 8; ++nf) {
            o[nf][0] *= al0; o[nf][1] *= al0;
            o[nf][2] *= al1; o[nf][3] *= al1;
        }

        // ---- O += P @ Vt (3-pass split, P fragments built in registers) ----
        const uint32_t vhB = sb + VBASE + (uint32_t)(s * 2) * AVTILE + offBv;
        const uint32_t vlB = vhB + AVTILE;
        #pragma unroll
        for (int kk = 0; kk < 8; ++kk) {
            uint32_t ph[4], pl[4];
            #pragma unroll
            for (int u = 0; u < 2; ++u) {         // u=0: nfrag 2kk, u=1: 2kk+1
                const float* cc = c[2 * kk + u];
                float r[4];
                __nv_bfloat16 hb[4];
                #pragma unroll
                for (int e = 0; e < 4; ++e) {
                    hb[e] = __float2bfloat16(cc[e]);
                    r[e]  = cc[e] - __bfloat162float(hb[e]);
                }
                ph[2 * u]     = pack_bf16(__bfloat162float(hb[0]),
                                          __bfloat162float(hb[1]));
                ph[2 * u + 1] = pack_bf16(__bfloat162float(hb[2]),
                                          __bfloat162float(hb[3]));
                pl[2 * u]     = pack_bf16(r[0], r[1]);
                pl[2 * u + 1] = pack_bf16(r[2], r[3]);
            }
            // a-frag order must be (r,k0-7),(r+8,k0-7),(r,k8-15),(r+8,k8-15)
            uint32_t pah[4] = {ph[0], ph[1], ph[2], ph[3]};
            uint32_t pal[4] = {pl[0], pl[1], pl[2], pl[3]};
            #pragma unroll
            for (int p = 0; p < 4; ++p) {
                const uint32_t d = (uint32_t)(p * 16) * VPITCH + (uint32_t)kk * 32;
                uint32_t vh[4], vl[4];
                LDMATRIX_X4(vh[0], vh[1], vh[2], vh[3], vhB + d);
                LDMATRIX_X4(vl[0], vl[1], vl[2], vl[3], vlB + d);
                MMA16816(o[2 * p], pah, vh);
                MMA16816(o[2 * p], pah, vl);
                MMA16816(o[2 * p], pal, vh);
                MMA16816(o[2 * p + 1], pah, vh + 2);
                MMA16816(o[2 * p + 1], pah, vl + 2);
                MMA16816(o[2 * p + 1], pal, vh + 2);
            }
        }
        __syncthreads();
        if (ck + 2 < 8)
            attn_load_kv(sb, s, Kh, Kl, Vth, Vtl, qkBase, vBase, m, ck + 2, tid);
    }

    // ---- epilogue: normalize, split bf16, store to Oh/Ol token-major ----
    const float inv0 = 1.0f / lsum0, inv1 = 1.0f / lsum1;
    const int j0 = qb * 128 + w * 16 + (l >> 2);
    const int tok0 = j0 * MM + m, tok1 = (j0 + 8) * MM + m;
    #pragma unroll
    for (int nf = 0; nf < 8; ++nf) {
        const int col = h * DK + nf * 8 + (l & 3) * 2;
        const size_t a0 = ((size_t)b * LL + tok0) * DD + col;
        const size_t a1 = ((size_t)b * LL + tok1) * DD + col;
        float f0 = o[nf][0] * inv0, f1 = o[nf][1] * inv0;
        float f2 = o[nf][2] * inv1, f3 = o[nf][3] * inv1;
        __nv_bfloat16 h0 = __float2bfloat16(f0), h1 = __float2bfloat16(f1);
        __nv_bfloat16 h2 = __float2bfloat16(f2), h3 = __float2bfloat16(f3);
        *reinterpret_cast<uint32_t*>(Oh + a0) =
            pack_bf16(__bfloat162float(h0), __bfloat162float(h1));
        *reinterpret_cast<uint32_t*>(Oh + a1) =
            pack_bf16(__bfloat162float(h2), __bfloat162float(h3));
        *reinterpret_cast<uint32_t*>(Ol + a0) =
            pack_bf16(f0 - __bfloat162float(h0), f1 - __bfloat162float(h1));
        *reinterpret_cast<uint32_t*>(Ol + a1) =
            pack_bf16(f2 - __bfloat162float(h2), f3 - __bfloat162float(h3));
    }
}

// ---------------------------------------------------------------------------
extern "C" void kernel_launch(void* const* d_in, const int* in_sizes, int n_in,
                              void* d_out, int out_size)
{
    const float* x  = (const float*)d_in[0];
    const float* Wq = (const float*)d_in[1];
    const float* bq = (const float*)d_in[2];
    const float* Wk = (const float*)d_in[3];
    const float* bk = (const float*)d_in[4];
    const float* Wv = (const float*)d_in[5];
    const float* bv = (const float*)d_in[6];
    const float* Wo = (const float*)d_in[7];
    const float* bo = (const float*)d_in[8];
    float* out = (float*)d_out;

    float *Qp, *Kp, *Vp;
    cudaGetSymbolAddress((void**)&Qp, g_Q);
    cudaGetSymbolAddress((void**)&Kp, g_K);
    cudaGetSymbolAddress((void**)&Vp, g_V);
    __nv_bfloat16 *xh, *xl, *Qhp, *Qlp, *Khp, *Klp, *Vthp, *Vtlp, *Ohp, *Olp,
                  *Wth, *Wtl;
    cudaGetSymbolAddress((void**)&xh, g_xh);
    cudaGetSymbolAddress((void**)&xl, g_xl);
    cudaGetSymbolAddress((void**)&Qhp, g_Qh);
    cudaGetSymbolAddress((void**)&Qlp, g_Ql);
    cudaGetSymbolAddress((void**)&Khp, g_Kh);
    cudaGetSymbolAddress((void**)&Klp, g_Kl);
    cudaGetSymbolAddress((void**)&Vthp, g_Vth);
    cudaGetSymbolAddress((void**)&Vtlp, g_Vtl);
    cudaGetSymbolAddress((void**)&Ohp, g_Oh);
    cudaGetSymbolAddress((void**)&Olp, g_Ol);
    cudaGetSymbolAddress((void**)&Wth, g_Wth);
    cudaGetSymbolAddress((void**)&Wtl, g_Wtl);

    const int cvtBlocks = (NTOK * DD) / (256 * 4);
    cvt_split<<<cvtBlocks, 256>>>(x, xh, xl, 1.0f);
    const dim3 wGrid(DD / 32, DD / 32);
    const dim3 wBlk(32, 8);
    cvt_w<<<wGrid, wBlk>>>(Wq, Wth + 0 * DD * DD, Wtl + 0 * DD * DD);
    cvt_w<<<wGrid, wBlk>>>(Wk, Wth + 1 * DD * DD, Wtl + 1 * DD * DD);
    cvt_w<<<wGrid, wBlk>>>(Wv, Wth + 2 * DD * DD, Wtl + 2 * DD * DD);
    cvt_w<<<wGrid, wBlk>>>(Wo, Wth + 3 * DD * DD, Wtl + 3 * DD * DD);

    const int gemmSmem = 2 * STAGEB;
    cudaFuncSetAttribute(gemm_mma, cudaFuncAttributeMaxDynamicSharedMemorySize,
                         gemmSmem);
    const dim3 gGrid(DD / 128, NTOK / 128);
    gemm_mma<<<gGrid, 256, gemmSmem>>>(xh, xl, Wth + 0 * DD * DD, Wtl + 0 * DD * DD, bq, Qp);
    gemm_mma<<<gGrid, 256, gemmSmem>>>(xh, xl, Wth + 1 * DD * DD, Wtl + 1 * DD * DD, bk, Kp);
    gemm_mma<<<gGrid, 256, gemmSmem>>>(xh, xl, Wth + 2 * DD * DD, Wtl + 2 * DD * DD, bv, Vp);

    // Q/K/V -> bf16 split (+ Q pre-scale, V transpose)
    cvt_split<<<cvtBlocks, 256>>>(Qp, Qhp, Qlp, 0.125f);
    cvt_split<<<cvtBlocks, 256>>>(Kp, Khp, Klp, 1.0f);
    v_cvt<<<dim3(NJ / 64, NSLICE), 256>>>(Vp, Vthp, Vtlp);

    // tensor-core flash attention
    cudaFuncSetAttribute(attn_mma, cudaFuncAttributeMaxDynamicSharedMemorySize,
                         ATT_SMEM);
    attn_mma<<<dim3(8, NSLICE), 256, ATT_SMEM>>>(Qhp, Qlp, Khp, Klp,
                                                 Vthp, Vtlp, Ohp, Olp);

    // output projection
    gemm_mma<<<gGrid, 256, gemmSmem>>>(Ohp, Olp, Wth + 3 * DD * DD,
                                       Wtl + 3 * DD * DD, bo, out);
}

// round 5
// speedup vs baseline: 2.8524x; 1.0440x over previous
#include <cuda_runtime.h>
#include <cuda_bf16.h>
#include <cstdint>

// Problem constants
#define BB 4
#define LL 4096
#define DD 1024
#define HH 16
#define MM 4
#define DK 64
#define NTOK (BB * LL)          // 16384
#define NSLICE (BB * HH * MM)   // 256
#define NJ (LL / MM)            // 1024 tokens per slice

// ---------------- scratch (__device__ globals; no cudaMalloc allowed) -------
__device__ float g_V[(size_t)NTOK * DD];
__device__ __nv_bfloat16 g_xh[(size_t)NTOK * DD];
__device__ __nv_bfloat16 g_xl[(size_t)NTOK * DD];
__device__ __nv_bfloat16 g_Qh[(size_t)NTOK * DD];
__device__ __nv_bfloat16 g_Ql[(size_t)NTOK * DD];
__device__ __nv_bfloat16 g_Kh[(size_t)NTOK * DD];
__device__ __nv_bfloat16 g_Kl[(size_t)NTOK * DD];
__device__ __nv_bfloat16 g_Vth[(size_t)NSLICE * DK * NJ];  // [slice][d][j]
__device__ __nv_bfloat16 g_Vtl[(size_t)NSLICE * DK * NJ];
__device__ __nv_bfloat16 g_Oh[(size_t)NTOK * DD];
__device__ __nv_bfloat16 g_Ol[(size_t)NTOK * DD];
__device__ __nv_bfloat16 g_Wth[4 * DD * DD];   // W^T hi (N-major: [n][k])
__device__ __nv_bfloat16 g_Wtl[4 * DD * DD];   // W^T lo

// ---------------- PTX helpers (sm_80-level only) ----------------------------
__device__ __forceinline__ uint32_t smem_u32(const void* p) {
    uint32_t a;
    asm("{ .reg .u64 t; cvta.to.shared.u64 t, %1; cvt.u32.u64 %0, t; }"
        : "=r"(a) : "l"(p));
    return a;
}
#define CP_ASYNC16(dst, src) \
    asm volatile("cp.async.cg.shared.global [%0], [%1], 16;" \
                 :: "r"(dst), "l"(src) : "memory")
#define CP_COMMIT() asm volatile("cp.async.commit_group;" ::: "memory")
#define CP_WAIT1()  asm volatile("cp.async.wait_group 1;" ::: "memory")
#define CP_WAIT0()  asm volatile("cp.async.wait_group 0;" ::: "memory")

#define LDMATRIX_X4(r0, r1, r2, r3, addr)                                     \
    asm volatile("ldmatrix.sync.aligned.m8n8.x4.shared.b16 {%0,%1,%2,%3}, [%4];" \
                 : "=r"(r0), "=r"(r1), "=r"(r2), "=r"(r3) : "r"(addr))

#define MMA16816(c, a, b)                                                     \
    asm volatile("mma.sync.aligned.m16n8k16.row.col.f32.bf16.bf16.f32 "       \
                 "{%0,%1,%2,%3}, {%4,%5,%6,%7}, {%8,%9}, {%0,%1,%2,%3};"      \
                 : "+f"((c)[0]), "+f"((c)[1]), "+f"((c)[2]), "+f"((c)[3])     \
                 : "r"((a)[0]), "r"((a)[1]), "r"((a)[2]), "r"((a)[3]),        \
                   "r"((b)[0]), "r"((b)[1]))

__device__ __forceinline__ uint32_t pack_bf16(float lo, float hi) {
    uint32_t r;
    asm("cvt.rn.bf16x2.f32 %0, %1, %2;" : "=r"(r) : "f"(hi), "f"(lo));
    return r;
}

// ---------------- conversion kernels ----------------------------------------
__global__ __launch_bounds__(256) void cvt_split(
    const float* __restrict__ X, __nv_bfloat16* __restrict__ Hh,
    __nv_bfloat16* __restrict__ Ll, float scale)
{
    size_t i = ((size_t)blockIdx.x * 256 + threadIdx.x) * 4;
    float4 v = *reinterpret_cast<const float4*>(X + i);
    __nv_bfloat16 h[4], l[4];
    float f[4] = {v.x * scale, v.y * scale, v.z * scale, v.w * scale};
    #pragma unroll
    for (int j = 0; j < 4; ++j) {
        h[j] = __float2bfloat16(f[j]);
        l[j] = __float2bfloat16(f[j] - __bfloat162float(h[j]));
    }
    *reinterpret_cast<uint2*>(Hh + i) = *reinterpret_cast<uint2*>(h);
    *reinterpret_cast<uint2*>(Ll + i) = *reinterpret_cast<uint2*>(l);
}

// transpose + split:  Wt[n][k] = W[k][n]
__global__ __launch_bounds__(256) void cvt_w(
    const float* __restrict__ W, __nv_bfloat16* __restrict__ Th,
    __nv_bfloat16* __restrict__ Tl)
{
    __shared__ float t[32][33];
    const int k0 = blockIdx.y * 32, n0 = blockIdx.x * 32;
    const int tx = threadIdx.x, ty = threadIdx.y;   // 32 x 8
    #pragma unroll
    for (int j = 0; j < 4; ++j)
        t[ty + 8 * j][tx] = W[(size_t)(k0 + ty + 8 * j) * DD + n0 + tx];
    __syncthreads();
    #pragma unroll
    for (int j = 0; j < 4; ++j) {
        const int n = ty + 8 * j;
        float w = t[tx][n];
        __nv_bfloat16 h = __float2bfloat16(w);
        __nv_bfloat16 l = __float2bfloat16(w - __bfloat162float(h));
        Th[(size_t)(n0 + n) * DD + k0 + tx] = h;
        Tl[(size_t)(n0 + n) * DD + k0 + tx] = l;
    }
}

// V transpose per slice: V fp32 [tok][h*64+d] -> Vt [slice][d][j] bf16 hi/lo
__global__ __launch_bounds__(256) void v_cvt(
    const float* __restrict__ V, __nv_bfloat16* __restrict__ Vth,
    __nv_bfloat16* __restrict__ Vtl)
{
    __shared__ float t[64][65];
    const int jb = blockIdx.x;
    const int sl = blockIdx.y;
    const int m = sl & 3, h = (sl >> 2) & 15, b = sl >> 6;
    const size_t base = ((size_t)b * LL) * DD + (size_t)h * DK;
    const int tid = threadIdx.x;
    {
        const int jj = tid >> 2;
        const int d0 = (tid & 3) * 16;
        const int tok = (jb * 64 + jj) * MM + m;
        const float* src = V + base + (size_t)tok * DD + d0;
        #pragma unroll
        for (int i = 0; i < 4; ++i) {
            float4 v4 = *reinterpret_cast<const float4*>(src + i * 4);
            t[jj][d0 + i * 4 + 0] = v4.x;
            t[jj][d0 + i * 4 + 1] = v4.y;
            t[jj][d0 + i * 4 + 2] = v4.z;
            t[jj][d0 + i * 4 + 3] = v4.w;
        }
    }
    __syncthreads();
    {
        const int d  = tid >> 2;
        const int j0 = (tid & 3) * 16;
        const size_t dst = ((size_t)sl * DK + d) * NJ + jb * 64 + j0;
        #pragma unroll
        for (int i = 0; i < 16; i += 4) {
            float f[4];
            #pragma unroll
            for (int u = 0; u < 4; ++u) f[u] = t[j0 + i + u][d];
            __nv_bfloat16 hh[4], ll[4];
            #pragma unroll
            for (int u = 0; u < 4; ++u) {
                hh[u] = __float2bfloat16(f[u]);
                ll[u] = __float2bfloat16(f[u] - __bfloat162float(hh[u]));
            }
            *reinterpret_cast<uint2*>(Vth + dst + i) = *reinterpret_cast<uint2*>(hh);
            *reinterpret_cast<uint2*>(Vtl + dst + i) = *reinterpret_cast<uint2*>(ll);
        }
    }
}

// ---------------- mma.sync split-bf16 GEMM ----------------------------------
#define GKC   64
#define NCH   (DD / GKC)        // 16
#define PITCH 72
#define PITCHB (PITCH * 2)      // 144 B
#define TILEB (128 * PITCHB)    // 18432
#define STAGEB (4 * TILEB)

__device__ __forceinline__ void g_load_chunk(
    uint32_t sb, int s,
    const __nv_bfloat16* __restrict__ Ah, const __nv_bfloat16* __restrict__ Al,
    const __nv_bfloat16* __restrict__ Bh, const __nv_bfloat16* __restrict__ Bl,
    int M0, int N0, int ck, int tid)
{
    const __nv_bfloat16* bases[4] = {Ah, Al, Bh, Bl};
    const int r0s[4] = {M0, M0, N0, N0};
    #pragma unroll
    for (int t = 0; t < 4; ++t) {
        const __nv_bfloat16* base = bases[t];
        const int r0 = r0s[t];
        const uint32_t tb = sb + (uint32_t)s * STAGEB + (uint32_t)t * TILEB;
        #pragma unroll
        for (int i = 0; i < 4; ++i) {
            const int idx = i * 256 + tid;
            const int row = idx >> 3, c = idx & 7;
            const void* g = base + (size_t)(r0 + row) * DD + ck * GKC + c * 8;
            CP_ASYNC16(tb + row * PITCHB + c * 16, g);
        }
    }
    CP_COMMIT();
}

// EPI = 0: fp32 output; EPI = 1: split bf16 hi/lo output (scaled)
template<int EPI>
__global__ __launch_bounds__(256) void gemm_mma_t(
    const __nv_bfloat16* __restrict__ Ah, const __nv_bfloat16* __restrict__ Al,
    const __nv_bfloat16* __restrict__ Bh, const __nv_bfloat16* __restrict__ Bl,
    const float* __restrict__ bias, float* __restrict__ Cf,
    __nv_bfloat16* __restrict__ Ch, __nv_bfloat16* __restrict__ Cl, float scale)
{
    extern __shared__ char smem[];
    const uint32_t sb = smem_u32(smem);
    const int tid = threadIdx.x;
    const int wid = tid >> 5, l = tid & 31;
    const int wm = (wid >> 2) * 64;
    const int wn = (wid & 3) * 32;
    const int M0 = blockIdx.y * 128, N0 = blockIdx.x * 128;

    float c[4][4][4];
    #pragma unroll
    for (int mf = 0; mf < 4; ++mf)
        #pragma unroll
        for (int nf = 0; nf < 4; ++nf)
            #pragma unroll
            for (int e = 0; e < 4; ++e) c[mf][nf][e] = 0.f;

    const uint32_t offA = (uint32_t)(wm + (l & 15)) * PITCHB + ((l >> 4) << 4);
    const uint32_t offB = (uint32_t)(wn + (l & 7) + ((l >> 4) << 3)) * PITCHB
                        + (((l >> 3) & 1) << 4);

    g_load_chunk(sb, 0, Ah, Al, Bh, Bl, M0, N0, 0, tid);
    g_load_chunk(sb, 1, Ah, Al, Bh, Bl, M0, N0, 1, tid);

    for (int ck = 0; ck < NCH; ++ck) {
        const int s = ck & 1;
        if (ck == NCH - 1) CP_WAIT0(); else CP_WAIT1();
        __syncthreads();

        const uint32_t stg = sb + (uint32_t)s * STAGEB;
        const uint32_t aH = stg + offA;
        const uint32_t aL = stg + TILEB + offA;
        const uint32_t bH = stg + 2 * TILEB + offB;
        const uint32_t bL = stg + 3 * TILEB + offB;

        #pragma unroll
        for (int ks = 0; ks < 4; ++ks) {
            const uint32_t kb = (uint32_t)ks * 32;
            uint32_t ah[4][4], al[4][4], bh[4][2], bl[4][2];
            #pragma unroll
            for (int mf = 0; mf < 4; ++mf) {
                const uint32_t d = (uint32_t)(mf * 16) * PITCHB + kb;
                LDMATRIX_X4(ah[mf][0], ah[mf][1], ah[mf][2], ah[mf][3], aH + d);
                LDMATRIX_X4(al[mf][0], al[mf][1], al[mf][2], al[mf][3], aL + d);
            }
            #pragma unroll
            for (int nh = 0; nh < 2; ++nh) {
                const uint32_t d = (uint32_t)(nh * 16) * PITCHB + kb;
                LDMATRIX_X4(bh[nh * 2][0], bh[nh * 2][1],
                            bh[nh * 2 + 1][0], bh[nh * 2 + 1][1], bH + d);
                LDMATRIX_X4(bl[nh * 2][0], bl[nh * 2][1],
                            bl[nh * 2 + 1][0], bl[nh * 2 + 1][1], bL + d);
            }
            #pragma unroll
            for (int mf = 0; mf < 4; ++mf)
                #pragma unroll
                for (int nf = 0; nf < 4; ++nf) {
                    MMA16816(c[mf][nf], ah[mf], bh[nf]);
                    MMA16816(c[mf][nf], ah[mf], bl[nf]);
                    MMA16816(c[mf][nf], al[mf], bh[nf]);
                }
        }
        __syncthreads();
        if (ck + 2 < NCH)
            g_load_chunk(sb, s, Ah, Al, Bh, Bl, M0, N0, ck + 2, tid);
    }

    #pragma unroll
    for (int mf = 0; mf < 4; ++mf) {
        const int r0 = M0 + wm + mf * 16 + (l >> 2);
        #pragma unroll
        for (int nf = 0; nf < 4; ++nf) {
            const int col = N0 + wn + nf * 8 + (l & 3) * 2;
            const float2 bi = *reinterpret_cast<const float2*>(bias + col);
            float f[4] = {c[mf][nf][0] + bi.x, c[mf][nf][1] + bi.y,
                          c[mf][nf][2] + bi.x, c[mf][nf][3] + bi.y};
            if (EPI == 0) {
                *reinterpret_cast<float2*>(Cf + (size_t)r0 * DD + col) =
                    make_float2(f[0], f[1]);
                *reinterpret_cast<float2*>(Cf + (size_t)(r0 + 8) * DD + col) =
                    make_float2(f[2], f[3]);
            } else {
                #pragma unroll
                for (int e = 0; e < 4; ++e) f[e] *= scale;
                __nv_bfloat16 hb[4];
                float r[4];
                #pragma unroll
                for (int e = 0; e < 4; ++e) {
                    hb[e] = __float2bfloat16(f[e]);
                    r[e]  = f[e] - __bfloat162float(hb[e]);
                }
                const size_t a0 = (size_t)r0 * DD + col;
                const size_t a1 = (size_t)(r0 + 8) * DD + col;
                *reinterpret_cast<uint32_t*>(Ch + a0) =
                    pack_bf16(__bfloat162float(hb[0]), __bfloat162float(hb[1]));
                *reinterpret_cast<uint32_t*>(Ch + a1) =
                    pack_bf16(__bfloat162float(hb[2]), __bfloat162float(hb[3]));
                *reinterpret_cast<uint32_t*>(Cl + a0) = pack_bf16(r[0], r[1]);
                *reinterpret_cast<uint32_t*>(Cl + a1) = pack_bf16(r[2], r[3]);
            }
        }
    }
}

// ---------------- tensor-core flash attention (256q x 64k tiles) ------------
// Grid: x = qblock (4 x 256 q rows), y = slice (256). 8 warps x 32 q rows.
#define AP 144                    // row pitch bytes (64 bf16 + 16 pad)
#define QTILE (256 * AP)          // 36864 per tensor
#define KTILE (64 * AP)           // 9216 per tensor
#define KBASE (2 * QTILE)         // 73728
#define VBASE (KBASE + 4 * KTILE) // 110592
#define ATT_SMEM (VBASE + 4 * KTILE)  // 147456

__device__ __forceinline__ void attn_load_kv(
    uint32_t sb, int s, const __nv_bfloat16* __restrict__ Kh,
    const __nv_bfloat16* __restrict__ Kl, const __nv_bfloat16* __restrict__ Vth,
    const __nv_bfloat16* __restrict__ Vtl, size_t qkBase, size_t vBase,
    int m, int ck, int tid)
{
    const __nv_bfloat16* kb[2] = {Kh, Kl};
    #pragma unroll
    for (int t = 0; t < 2; ++t) {
        const uint32_t tile = sb + KBASE + (uint32_t)(s * 2 + t) * KTILE;
        #pragma unroll
        for (int i = 0; i < 2; ++i) {
            const int idx = i * 256 + tid;          // 0..511
            const int row = idx >> 3, c = idx & 7;
            const int tok = (ck * 64 + row) * MM + m;
            const void* g = kb[t] + qkBase + (size_t)tok * DD + c * 8;
            CP_ASYNC16(tile + row * AP + c * 16, g);
        }
    }
    const __nv_bfloat16* vb[2] = {Vth, Vtl};
    #pragma unroll
    for (int t = 0; t < 2; ++t) {
        const uint32_t tile = sb + VBASE + (uint32_t)(s * 2 + t) * KTILE;
        #pragma unroll
        for (int i = 0; i < 2; ++i) {
            const int idx = i * 256 + tid;
            const int row = idx >> 3, c = idx & 7;  // row = d, c*8 = j offset
            const void* g = vb[t] + vBase + (size_t)row * NJ + ck * 64 + c * 8;
            CP_ASYNC16(tile + row * AP + c * 16, g);
        }
    }
    CP_COMMIT();
}

__global__ __launch_bounds__(256) void attn_mma(
    const __nv_bfloat16* __restrict__ Qh, const __nv_bfloat16* __restrict__ Ql,
    const __nv_bfloat16* __restrict__ Kh, const __nv_bfloat16* __restrict__ Kl,
    const __nv_bfloat16* __restrict__ Vth, const __nv_bfloat16* __restrict__ Vtl,
    __nv_bfloat16* __restrict__ Oh, __nv_bfloat16* __restrict__ Ol)
{
    extern __shared__ char smem[];
    const uint32_t sb = smem_u32(smem);
    const int tid = threadIdx.x, w = tid >> 5, l = tid & 31;
    const int qb = blockIdx.x;          // 0..3
    const int sl = blockIdx.y;          // 0..255
    const int m = sl & 3, h = (sl >> 2) & 15, b = sl >> 6;

    const size_t qkBase = ((size_t)b * LL) * DD + (size_t)h * DK;
    const size_t vBase  = (size_t)sl * DK * NJ;

    // Q tiles (hi, lo) loaded once (in cp group 0)
    {
        const __nv_bfloat16* qB[2] = {Qh, Ql};
        #pragma unroll
        for (int t = 0; t < 2; ++t) {
            const uint32_t tile = sb + (uint32_t)t * QTILE;
            #pragma unroll
            for (int i = 0; i < 8; ++i) {
                const int idx = i * 256 + tid;      // 0..2047
                const int row = idx >> 3, c = idx & 7;
                const int tok = (qb * 256 + row) * MM + m;
                const void* g = qB[t] + qkBase + (size_t)tok * DD + c * 8;
                CP_ASYNC16(tile + row * AP + c * 16, g);
            }
        }
    }
    attn_load_kv(sb, 0, Kh, Kl, Vth, Vtl, qkBase, vBase, m, 0, tid);
    attn_load_kv(sb, 1, Kh, Kl, Vth, Vtl, qkBase, vBase, m, 1, tid);

    const uint32_t offA = (uint32_t)(w * 32 + (l & 15)) * AP + ((l >> 4) << 4);
    const uint32_t offB = (uint32_t)((l & 7) + ((l >> 4) << 3)) * AP
                        + (((l >> 3) & 1) << 4);

    float o[2][8][4];
    #pragma unroll
    for (int mf = 0; mf < 2; ++mf)
        #pragma unroll
        for (int nf = 0; nf < 8; ++nf)
            #pragma unroll
            for (int e = 0; e < 4; ++e) o[mf][nf][e] = 0.f;
    float mrow[4] = {-1e30f, -1e30f, -1e30f, -1e30f};
    float lsum[4] = {0.f, 0.f, 0.f, 0.f};

    for (int ck = 0; ck < 16; ++ck) {
        const int s = ck & 1;
        if (ck == 15) CP_WAIT0(); else CP_WAIT1();
        __syncthreads();

        // ---- S = Q @ K^T (3-pass split): 32 q x 64 k per warp ----
        float c[2][8][4];
        #pragma unroll
        for (int mf = 0; mf < 2; ++mf)
            #pragma unroll
            for (int nf = 0; nf < 8; ++nf)
                #pragma unroll
                for (int e = 0; e < 4; ++e) c[mf][nf][e] = 0.f;

        const uint32_t qhA = sb + offA;
        const uint32_t qlA = sb + QTILE + offA;
        const uint32_t khB = sb + KBASE + (uint32_t)(s * 2) * KTILE + offB;
        const uint32_t klB = khB + KTILE;

        #pragma unroll
        for (int ks = 0; ks < 4; ++ks) {
            const uint32_t kb = (uint32_t)ks * 32;
            uint32_t ah[2][4], al[2][4];
            #pragma unroll
            for (int mf = 0; mf < 2; ++mf) {
                const uint32_t d = (uint32_t)(mf * 16) * AP + kb;
                LDMATRIX_X4(ah[mf][0], ah[mf][1], ah[mf][2], ah[mf][3], qhA + d);
                LDMATRIX_X4(al[mf][0], al[mf][1], al[mf][2], al[mf][3], qlA + d);
            }
            #pragma unroll
            for (int p = 0; p < 4; ++p) {
                const uint32_t d = (uint32_t)(p * 16) * AP + kb;
                uint32_t bh[4], bl[4];
                LDMATRIX_X4(bh[0], bh[1], bh[2], bh[3], khB + d);
                LDMATRIX_X4(bl[0], bl[1], bl[2], bl[3], klB + d);
                #pragma unroll
                for (int mf = 0; mf < 2; ++mf) {
                    MMA16816(c[mf][2 * p], ah[mf], bh);
                    MMA16816(c[mf][2 * p], ah[mf], bl);
                    MMA16816(c[mf][2 * p], al[mf], bh);
                    MMA16816(c[mf][2 * p + 1], ah[mf], bh + 2);
                    MMA16816(c[mf][2 * p + 1], ah[mf], bl + 2);
                    MMA16816(c[mf][2 * p + 1], al[mf], bh + 2);
                }
            }
        }

        // ---- online softmax (per mf: two rows r, r+8 per thread) ----
        #pragma unroll
        for (int mf = 0; mf < 2; ++mf) {
            float mx0 = -1e30f, mx1 = -1e30f;
            #pragma unroll
            for (int nf = 0; nf < 8; ++nf) {
                mx0 = fmaxf(mx0, fmaxf(c[mf][nf][0], c[mf][nf][1]));
                mx1 = fmaxf(mx1, fmaxf(c[mf][nf][2], c[mf][nf][3]));
            }
            mx0 = fmaxf(mx0, __shfl_xor_sync(0xffffffffu, mx0, 1));
            mx0 = fmaxf(mx0, __shfl_xor_sync(0xffffffffu, mx0, 2));
            mx1 = fmaxf(mx1, __shfl_xor_sync(0xffffffffu, mx1, 1));
            mx1 = fmaxf(mx1, __shfl_xor_sync(0xffffffffu, mx1, 2));
            const float mn0 = fmaxf(mrow[2 * mf], mx0);
            const float mn1 = fmaxf(mrow[2 * mf + 1], mx1);
            const float al0 = __expf(mrow[2 * mf] - mn0);
            const float al1 = __expf(mrow[2 * mf + 1] - mn1);
            mrow[2 * mf] = mn0; mrow[2 * mf + 1] = mn1;
            float s0 = 0.f, s1 = 0.f;
            #pragma unroll
            for (int nf = 0; nf < 8; ++nf) {
                c[mf][nf][0] = __expf(c[mf][nf][0] - mn0);
                c[mf][nf][1] = __expf(c[mf][nf][1] - mn0);
                c[mf][nf][2] = __expf(c[mf][nf][2] - mn1);
                c[mf][nf][3] = __expf(c[mf][nf][3] - mn1);
                s0 += c[mf][nf][0] + c[mf][nf][1];
                s1 += c[mf][nf][2] + c[mf][nf][3];
            }
            s0 += __shfl_xor_sync(0xffffffffu, s0, 1);
            s0 += __shfl_xor_sync(0xffffffffu, s0, 2);
            s1 += __shfl_xor_sync(0xffffffffu, s1, 1);
            s1 += __shfl_xor_sync(0xffffffffu, s1, 2);
            lsum[2 * mf] = lsum[2 * mf] * al0 + s0;
            lsum[2 * mf + 1] = lsum[2 * mf + 1] * al1 + s1;
            #pragma unroll
            for (int nf = 0; nf < 8; ++nf) {
                o[mf][nf][0] *= al0; o[mf][nf][1] *= al0;
                o[mf][nf][2] *= al1; o[mf][nf][3] *= al1;
            }
        }

        // ---- O += P @ Vt (3-pass split, P frags in registers) ----
        const uint32_t vhB = sb + VBASE + (uint32_t)(s * 2) * KTILE + offB;
        const uint32_t vlB = vhB + KTILE;
        #pragma unroll
        for (int kk = 0; kk < 4; ++kk) {          // 4 groups of 16 keys
            uint32_t pah[2][4], pal[2][4];
            #pragma unroll
            for (int mf = 0; mf < 2; ++mf)
                #pragma unroll
                for (int u = 0; u < 2; ++u) {
                    const float* cc = c[mf][2 * kk + u];
                    __nv_bfloat16 hb[4];
                    float r[4];
                    #pragma unroll
                    for (int e = 0; e < 4; ++e) {
                        hb[e] = __float2bfloat16(cc[e]);
                        r[e]  = cc[e] - __bfloat162float(hb[e]);
                    }
                    pah[mf][2 * u]     = pack_bf16(__bfloat162float(hb[0]),
                                                   __bfloat162float(hb[1]));
                    pah[mf][2 * u + 1] = pack_bf16(__bfloat162float(hb[2]),
                                                   __bfloat162float(hb[3]));
                    pal[mf][2 * u]     = pack_bf16(r[0], r[1]);
                    pal[mf][2 * u + 1] = pack_bf16(r[2], r[3]);
                }
            #pragma unroll
            for (int p = 0; p < 4; ++p) {         // 4 groups of 16 d
                const uint32_t d = (uint32_t)(p * 16) * AP + (uint32_t)kk * 32;
                uint32_t vh[4], vl[4];
                LDMATRIX_X4(vh[0], vh[1], vh[2], vh[3], vhB + d);
                LDMATRIX_X4(vl[0], vl[1], vl[2], vl[3], vlB + d);
                #pragma unroll
                for (int mf = 0; mf < 2; ++mf) {
                    MMA16816(o[mf][2 * p], pah[mf], vh);
                    MMA16816(o[mf][2 * p], pah[mf], vl);
                    MMA16816(o[mf][2 * p], pal[mf], vh);
                    MMA16816(o[mf][2 * p + 1], pah[mf], vh + 2);
                    MMA16816(o[mf][2 * p + 1], pah[mf], vl + 2);
                    MMA16816(o[mf][2 * p + 1], pal[mf], vh + 2);
                }
            }
        }
        __syncthreads();
        if (ck + 2 < 16)
            attn_load_kv(sb, s, Kh, Kl, Vth, Vtl, qkBase, vBase, m, ck + 2, tid);
    }

    // ---- epilogue: normalize, split bf16, store to Oh/Ol token-major ----
    #pragma unroll
    for (int mf = 0; mf < 2; ++mf) {
        const float inv0 = 1.0f / lsum[2 * mf];
        const float inv1 = 1.0f / lsum[2 * mf + 1];
        const int j0 = qb * 256 + w * 32 + mf * 16 + (l >> 2);
        const int tok0 = j0 * MM + m, tok1 = (j0 + 8) * MM + m;
        #pragma unroll
        for (int nf = 0; nf < 8; ++nf) {
            const int col = h * DK + nf * 8 + (l & 3) * 2;
            const size_t a0 = ((size_t)b * LL + tok0) * DD + col;
            const size_t a1 = ((size_t)b * LL + tok1) * DD + col;
            float f0 = o[mf][nf][0] * inv0, f1 = o[mf][nf][1] * inv0;
            float f2 = o[mf][nf][2] * inv1, f3 = o[mf][nf][3] * inv1;
            __nv_bfloat16 h0 = __float2bfloat16(f0), h1 = __float2bfloat16(f1);
            __nv_bfloat16 h2 = __float2bfloat16(f2), h3 = __float2bfloat16(f3);
            *reinterpret_cast<uint32_t*>(Oh + a0) =
                pack_bf16(__bfloat162float(h0), __bfloat162float(h1));
            *reinterpret_cast<uint32_t*>(Oh + a1) =
                pack_bf16(__bfloat162float(h2), __bfloat162float(h3));
            *reinterpret_cast<uint32_t*>(Ol + a0) =
                pack_bf16(f0 - __bfloat162float(h0), f1 - __bfloat162float(h1));
            *reinterpret_cast<uint32_t*>(Ol + a1) =
                pack_bf16(f2 - __bfloat162float(h2), f3 - __bfloat162float(h3));
        }
    }
}

// ---------------------------------------------------------------------------
extern "C" void kernel_launch(void* const* d_in, const int* in_sizes, int n_in,
                              void* d_out, int out_size)
{
    const float* x  = (const float*)d_in[0];
    const float* Wq = (const float*)d_in[1];
    const float* bq = (const float*)d_in[2];
    const float* Wk = (const float*)d_in[3];
    const float* bk = (const float*)d_in[4];
    const float* Wv = (const float*)d_in[5];
    const float* bv = (const float*)d_in[6];
    const float* Wo = (const float*)d_in[7];
    const float* bo = (const float*)d_in[8];
    float* out = (float*)d_out;

    float* Vp;
    cudaGetSymbolAddress((void**)&Vp, g_V);
    __nv_bfloat16 *xh, *xl, *Qhp, *Qlp, *Khp, *Klp, *Vthp, *Vtlp, *Ohp, *Olp,
                  *Wth, *Wtl;
    cudaGetSymbolAddress((void**)&xh, g_xh);
    cudaGetSymbolAddress((void**)&xl, g_xl);
    cudaGetSymbolAddress((void**)&Qhp, g_Qh);
    cudaGetSymbolAddress((void**)&Qlp, g_Ql);
    cudaGetSymbolAddress((void**)&Khp, g_Kh);
    cudaGetSymbolAddress((void**)&Klp, g_Kl);
    cudaGetSymbolAddress((void**)&Vthp, g_Vth);
    cudaGetSymbolAddress((void**)&Vtlp, g_Vtl);
    cudaGetSymbolAddress((void**)&Ohp, g_Oh);
    cudaGetSymbolAddress((void**)&Olp, g_Ol);
    cudaGetSymbolAddress((void**)&Wth, g_Wth);
    cudaGetSymbolAddress((void**)&Wtl, g_Wtl);

    const int cvtBlocks = (NTOK * DD) / (256 * 4);
    cvt_split<<<cvtBlocks, 256>>>(x, xh, xl, 1.0f);
    const dim3 wGrid(DD / 32, DD / 32);
    const dim3 wBlk(32, 8);
    cvt_w<<<wGrid, wBlk>>>(Wq, Wth + 0 * DD * DD, Wtl + 0 * DD * DD);
    cvt_w<<<wGrid, wBlk>>>(Wk, Wth + 1 * DD * DD, Wtl + 1 * DD * DD);
    cvt_w<<<wGrid, wBlk>>>(Wv, Wth + 2 * DD * DD, Wtl + 2 * DD * DD);
    cvt_w<<<wGrid, wBlk>>>(Wo, Wth + 3 * DD * DD, Wtl + 3 * DD * DD);

    const int gemmSmem = 2 * STAGEB;
    cudaFuncSetAttribute(gemm_mma_t<0>,
                         cudaFuncAttributeMaxDynamicSharedMemorySize, gemmSmem);
    cudaFuncSetAttribute(gemm_mma_t<1>,
                         cudaFuncAttributeMaxDynamicSharedMemorySize, gemmSmem);
    const dim3 gGrid(DD / 128, NTOK / 128);
    // Q and K projections: fused split-bf16 epilogues (Q pre-scaled)
    gemm_mma_t<1><<<gGrid, 256, gemmSmem>>>(xh, xl, Wth + 0 * DD * DD,
        Wtl + 0 * DD * DD, bq, nullptr, Qhp, Qlp, 0.125f);
    gemm_mma_t<1><<<gGrid, 256, gemmSmem>>>(xh, xl, Wth + 1 * DD * DD,
        Wtl + 1 * DD * DD, bk, nullptr, Khp, Klp, 1.0f);
    // V projection: fp32 (consumed by v_cvt transpose)
    gemm_mma_t<0><<<gGrid, 256, gemmSmem>>>(xh, xl, Wth + 2 * DD * DD,
        Wtl + 2 * DD * DD, bv, Vp, nullptr, nullptr, 1.0f);
    v_cvt<<<dim3(NJ / 64, NSLICE), 256>>>(Vp, Vthp, Vtlp);

    // tensor-core flash attention
    cudaFuncSetAttribute(attn_mma,
                         cudaFuncAttributeMaxDynamicSharedMemorySize, ATT_SMEM);
    attn_mma<<<dim3(4, NSLICE), 256, ATT_SMEM>>>(Qhp, Qlp, Khp, Klp,
                                                 Vthp, Vtlp, Ohp, Olp);

    // output projection (fp32 out)
    gemm_mma_t<0><<<gGrid, 256, gemmSmem>>>(Ohp, Olp, Wth + 3 * DD * DD,
        Wtl + 3 * DD * DD, bo, out, nullptr, nullptr, 1.0f);
}